// round 15
// baseline (speedup 1.0000x reference)
#include <cuda_runtime.h>
#include <cstdint>

// InteractingSites: per-frame all-pairs soft-core Coulomb.
// DUAL-FRAME float4 tables (R12 memory layout) + SCALAR math using the
// rt_SMSP=1 FFMA-imm form for coordinate subtraction:
//   dx = fmaf(jx, -1.0f, rx)  ->  FFMA Rd, Rj, imm(-1), Rr   (full issue rate)
// vs FADD/3-reg FFMA at rt=2. ~75% of our stream is FMA-class, so the issue
// ceiling moves from ~57% to ~65%+.
//
// energy[f] = sum_{i<j} q_i q_j * rsqrt(|p_i-p_j|^2 + 1e-6)
//
// CTA = frame pair (A,B) = 4 warps x 32. Tiles T0..T3 (32 sites each).
// Shared: site[tile][0][m] = (xA,xB,yA,yB), site[tile][1][m] = (zA,zB,qA,qB)
// (float4, 16B lane stride -> conflict-free LDS.128; each loaded j-quad
// serves one pair in frame A and one in frame B).
//
// Enumeration per frame (each unordered pair exactly once), split across warps:
//  Rectangles: m = 0..31, 6 tile combos (a<b). Warp w: m in [8w, 8w+8).
//    Per m, j's processed one tile at a time (j3: rows 0,1,2; j2: rows 0,1;
//    j1: row 0) to keep register pressure low.
//  Triangles: per tile k: row k vs site[k][(l+dd)&31]; dd = 1..15 once each,
//    dd=16 masked to lanes 0..15. Warps 0..2: dd in [4w+1,4w+5); warp 3:
//    dd 13..15 + masked dd=16.
//
// Charge factoring: accX[k] += q_j * rsqrt(...); row charges re-read from the
// table at the end (no q row registers).

#define S_SITES 128
#define EPS_SOFT 1e-6f
#define FULLMASK 0xFFFFFFFFu

__device__ __forceinline__ float frsqrt(float x) {
    float r;
    asm("rsqrt.approx.f32 %0, %1;" : "=f"(r) : "f"(x));
    return r;
}

__global__ __launch_bounds__(S_SITES)
void interacting_sites_kernel(const float* __restrict__ positions,
                              const float* __restrict__ charges,
                              float* __restrict__ out,
                              int num_frames) {
    // [tile][0:(xA,xB,yA,yB) | 1:(zA,zB,qA,qB)][m]
    __shared__ float4 site[4][2][32];
    __shared__ float warp_sumA[4];
    __shared__ float warp_sumB[4];

    const int w = threadIdx.x >> 5;
    const int l = threadIdx.x & 31;

    const int fidA = blockIdx.x * 2;
    const bool hasB = (fidA + 1) < num_frames;
    const int fidB = hasB ? fidA + 1 : fidA;

    // Warp w builds tile w's table entries (both frames)
    {
        const long long ia = (long long)fidA * S_SITES + w * 32 + l;
        const long long ib = (long long)fidB * S_SITES + w * 32 + l;
        const float* pa = positions + ia * 3;
        const float* pb = positions + ib * 3;
        site[w][0][l] = make_float4(pa[0], pb[0], pa[1], pb[1]);
        site[w][1][l] = make_float4(pa[2], pb[2], charges[ia], charges[ib]);
    }
    __syncthreads();

    // Row registers: coords only (charges re-read at the end)
    float rxA[4], ryA[4], rzA[4], rxB[4], ryB[4], rzB[4];
#pragma unroll
    for (int k = 0; k < 4; ++k) {
        const float4 u = site[k][0][l];
        const float4 v = site[k][1][l];
        rxA[k] = u.x; rxB[k] = u.y;
        ryA[k] = u.z; ryB[k] = u.w;
        rzA[k] = v.x; rzB[k] = v.y;
    }

    float accA[4] = {0.f, 0.f, 0.f, 0.f};
    float accB[4] = {0.f, 0.f, 0.f, 0.f};

    // One packed group: row tile k vs j-quad (uj, vj); both frames.
    // Subtractions use fmaf(j, -1.0f, r): FFMA with immediate multiplier (rt=1).
#define GRP(k, uj, vj)                                                        \
    do {                                                                      \
        const float dxA = fmaf((uj).x, -1.0f, rxA[k]);                        \
        const float dxB = fmaf((uj).y, -1.0f, rxB[k]);                        \
        const float dyA = fmaf((uj).z, -1.0f, ryA[k]);                        \
        const float dyB = fmaf((uj).w, -1.0f, ryB[k]);                        \
        const float dzA = fmaf((vj).x, -1.0f, rzA[k]);                        \
        const float dzB = fmaf((vj).y, -1.0f, rzB[k]);                        \
        const float r2A = fmaf(dxA, dxA, fmaf(dyA, dyA, fmaf(dzA, dzA, EPS_SOFT))); \
        const float r2B = fmaf(dxB, dxB, fmaf(dyB, dyB, fmaf(dzB, dzB, EPS_SOFT))); \
        accA[k] = fmaf((vj).z, frsqrt(r2A), accA[k]);                         \
        accB[k] = fmaf((vj).w, frsqrt(r2B), accB[k]);                         \
    } while (0)

    // ── Rectangles: warp w handles m in [8w, 8w+8) — broadcast LDS ──
    const int m0 = w << 3;
#pragma unroll
    for (int i = 0; i < 8; ++i) {
        const int m = m0 + i;
        {   // j from tile 3: rows 0,1,2
            const float4 u3 = site[3][0][m], v3 = site[3][1][m];
            GRP(0, u3, v3);
            GRP(1, u3, v3);
            GRP(2, u3, v3);
        }
        {   // j from tile 2: rows 0,1
            const float4 u2 = site[2][0][m], v2 = site[2][1][m];
            GRP(0, u2, v2);
            GRP(1, u2, v2);
        }
        {   // j from tile 1: row 0
            const float4 u1 = site[1][0][m], v1 = site[1][1][m];
            GRP(0, u1, v1);
        }
    }

    // ── Triangles: warps 0..2 take dd in [4w+1,4w+5); warp 3: 13..15 + dd=16 ──
    const int dd0 = 1 + (w << 2);
#pragma unroll
    for (int i = 0; i < 4; ++i) {
        const int dd = dd0 + i;
        if (dd < 16) {
            const int m = (l + dd) & 31;
#pragma unroll
            for (int k = 0; k < 4; ++k) {
                const float4 u = site[k][0][m];
                const float4 v = site[k][1][m];
                GRP(k, u, v);
            }
        }
    }
    if (w == 3 && l < 16) {   // dd = 16: each opposite pair once
        const int m = l + 16;
#pragma unroll
        for (int k = 0; k < 4; ++k) {
            const float4 u = site[k][0][m];
            const float4 v = site[k][1][m];
            GRP(k, u, v);
        }
    }
#undef GRP

    // Row charges (re-read from table), applied once; reduce
    float sA = 0.f, sB = 0.f;
#pragma unroll
    for (int k = 0; k < 4; ++k) {
        const float4 v = site[k][1][l];
        sA = fmaf(v.z, accA[k], sA);
        sB = fmaf(v.w, accB[k], sB);
    }
#pragma unroll
    for (int o = 16; o > 0; o >>= 1) {
        sA += __shfl_xor_sync(FULLMASK, sA, o);
        sB += __shfl_xor_sync(FULLMASK, sB, o);
    }
    if (l == 0) {
        warp_sumA[w] = sA;
        warp_sumB[w] = sB;
    }
    __syncthreads();
    if (threadIdx.x == 0) {
        out[fidA] = (warp_sumA[0] + warp_sumA[1]) + (warp_sumA[2] + warp_sumA[3]);
        if (hasB)
            out[fidB] = (warp_sumB[0] + warp_sumB[1]) + (warp_sumB[2] + warp_sumB[3]);
    }
}

extern "C" void kernel_launch(void* const* d_in, const int* in_sizes, int n_in,
                              void* d_out, int out_size) {
    const float* positions = (const float*)d_in[0];  // [N,3] f32
    const float* charges   = (const float*)d_in[1];  // [N]   f32
    float* out = (float*)d_out;                      // [B]   f32

    const int num_frames = out_size;
    const int grid = (num_frames + 1) / 2;
    interacting_sites_kernel<<<grid, S_SITES>>>(positions, charges, out, num_frames);
}

// round 17
// speedup vs baseline: 1.6800x; 1.6800x over previous
#include <cuda_runtime.h>
#include <cstdint>

// InteractingSites: per-frame all-pairs soft-core Coulomb.
// R12 champion (dual-frame f32x2 + LDS broadcast) + 7 independent accumulator
// streams (6 rect combos + dedicated tri-row3) to break serial acc chains and
// raise in-warp ILP at unchanged instruction count.
//
// energy[f] = sum_{i<j} q_i q_j * rsqrt(|p_i-p_j|^2 + 1e-6)
//
// f32x2 lo half = frame A, hi half = frame B. CTA = frame pair = 4 warps x 32.
// Tiles T0..T3. Shared: site[tile][0][m]=(xx,yy), site[tile][1][m]=(zz,qq).
//
// Enumeration per frame (each unordered pair exactly once):
//  Rectangles: m = 0..31, 6 combos (a<b) -> streams a01,a02,a03,a12,a13,a23.
//    Warp w: m in [8w, 8w+8).
//  Triangles: per tile k, dd = 1..15 + masked dd=16; row-k terms go to a
//    stream whose ROW charge is k: row0->a01/a02 (alt), row1->a12/a13 (alt),
//    row2->a23, row3->t3. Warps 0..2: dd in [4w+1,4w+5); warp 3: 13..15+16m.
//
// Charge factoring: acc += q_j * rsqrt; row charges applied once:
//   E = q0*(a01+a02+a03) + q1*(a12+a13) + q2*a23 + q3*t3
//   (a03 carries rect row-0 terms only; t3 carries all row-3 tri terms).

#define S_SITES 128
#define EPS2_PACKED 0x358637BD358637BDULL  // (1e-6f, 1e-6f)
#define NEG1_PACKED 0xBF800000BF800000ULL  // (-1.0f, -1.0f)
#define ONE2_PACKED 0x3F8000003F800000ULL  // (1.0f, 1.0f)
#define FULLMASK 0xFFFFFFFFu

using u64 = unsigned long long;

__device__ __forceinline__ u64 pk2(float lo, float hi) {
    u64 r;
    asm("mov.b64 %0, {%1, %2};" : "=l"(r) : "f"(lo), "f"(hi));
    return r;
}
__device__ __forceinline__ void unpk2(u64 v, float& lo, float& hi) {
    asm("mov.b64 {%0, %1}, %2;" : "=f"(lo), "=f"(hi) : "l"(v));
}
__device__ __forceinline__ u64 fma2(u64 a, u64 b, u64 c) {
    u64 d;
    asm("fma.rn.f32x2 %0, %1, %2, %3;" : "=l"(d) : "l"(a), "l"(b), "l"(c));
    return d;
}
__device__ __forceinline__ u64 rsqrt2(u64 v) {
    float lo, hi;
    unpk2(v, lo, hi);
    float rl, rh;
    asm("rsqrt.approx.f32 %0, %1;" : "=f"(rl) : "f"(lo));
    asm("rsqrt.approx.f32 %0, %1;" : "=f"(rh) : "f"(hi));
    return pk2(rl, rh);
}

// acc += jq * rsqrt(|row - j|^2 + eps), elementwise on both frame halves.
__device__ __forceinline__ void grp(u64 rx, u64 ry, u64 rz,
                                    u64 jx, u64 jy, u64 jz, u64 jq,
                                    u64& acc) {
    u64 dx = fma2(jx, (u64)NEG1_PACKED, rx);
    u64 dy = fma2(jy, (u64)NEG1_PACKED, ry);
    u64 dz = fma2(jz, (u64)NEG1_PACKED, rz);
    u64 r2 = fma2(dz, dz, (u64)EPS2_PACKED);
    r2 = fma2(dy, dy, r2);
    r2 = fma2(dx, dx, r2);
    u64 rs = rsqrt2(r2);
    acc = fma2(jq, rs, acc);
}

__global__ __launch_bounds__(S_SITES)
void interacting_sites_kernel(const float* __restrict__ positions,
                              const float* __restrict__ charges,
                              float* __restrict__ out,
                              int num_frames) {
    __shared__ ulonglong2 site[4][2][32];
    __shared__ float warp_sumA[4];
    __shared__ float warp_sumB[4];

    const int w = threadIdx.x >> 5;
    const int l = threadIdx.x & 31;

    const int fidA = blockIdx.x * 2;
    const bool hasB = (fidA + 1) < num_frames;
    const int fidB = hasB ? fidA + 1 : fidA;

    // Warp w builds tile w's table entries (both frames)
    {
        const long long ia = (long long)fidA * S_SITES + w * 32 + l;
        const long long ib = (long long)fidB * S_SITES + w * 32 + l;
        const float* pa = positions + ia * 3;
        const float* pb = positions + ib * 3;
        const float qa = charges[ia];
        const float qb = charges[ib];
        site[w][0][l] = make_ulonglong2(pk2(pa[0], pb[0]), pk2(pa[1], pb[1]));
        site[w][1][l] = make_ulonglong2(pk2(pa[2], pb[2]), pk2(qa, qb));
    }
    __syncthreads();

    u64 rx[4], ry[4], rz[4], rq[4];
#pragma unroll
    for (int k = 0; k < 4; ++k) {
        const ulonglong2 u = site[k][0][l];
        const ulonglong2 v = site[k][1][l];
        rx[k] = u.x;
        ry[k] = u.y;
        rz[k] = v.x;
        rq[k] = v.y;
    }

    u64 a01 = 0ULL, a02 = 0ULL, a03 = 0ULL, a12 = 0ULL, a13 = 0ULL,
        a23 = 0ULL, t3 = 0ULL;

    // ── Rectangles: warp w handles m in [8w, 8w+8) — broadcast LDS ──
    const int m0 = w << 3;
#pragma unroll
    for (int i = 0; i < 8; ++i) {
        const int m = m0 + i;
        const ulonglong2 u1 = site[1][0][m], v1 = site[1][1][m];
        const ulonglong2 u2 = site[2][0][m], v2 = site[2][1][m];
        const ulonglong2 u3 = site[3][0][m], v3 = site[3][1][m];

        grp(rx[0], ry[0], rz[0], u1.x, u1.y, v1.x, v1.y, a01);
        grp(rx[0], ry[0], rz[0], u2.x, u2.y, v2.x, v2.y, a02);
        grp(rx[0], ry[0], rz[0], u3.x, u3.y, v3.x, v3.y, a03);
        grp(rx[1], ry[1], rz[1], u2.x, u2.y, v2.x, v2.y, a12);
        grp(rx[1], ry[1], rz[1], u3.x, u3.y, v3.x, v3.y, a13);
        grp(rx[2], ry[2], rz[2], u3.x, u3.y, v3.x, v3.y, a23);
    }

    // ── Triangles: warps 0..2 take dd in [4w+1,4w+5); warp 3: 13..15 + dd=16 ──
    const int dd0 = 1 + (w << 2);
#pragma unroll
    for (int i = 0; i < 4; ++i) {
        const int dd = dd0 + i;
        if (dd < 16) {
            const int m = (l + dd) & 31;
            const ulonglong2 u0 = site[0][0][m], v0 = site[0][1][m];
            const ulonglong2 u1 = site[1][0][m], v1 = site[1][1][m];
            const ulonglong2 u2 = site[2][0][m], v2 = site[2][1][m];
            const ulonglong2 u3 = site[3][0][m], v3 = site[3][1][m];
            if (i & 1) {
                grp(rx[0], ry[0], rz[0], u0.x, u0.y, v0.x, v0.y, a01);
                grp(rx[1], ry[1], rz[1], u1.x, u1.y, v1.x, v1.y, a12);
            } else {
                grp(rx[0], ry[0], rz[0], u0.x, u0.y, v0.x, v0.y, a02);
                grp(rx[1], ry[1], rz[1], u1.x, u1.y, v1.x, v1.y, a13);
            }
            grp(rx[2], ry[2], rz[2], u2.x, u2.y, v2.x, v2.y, a23);
            grp(rx[3], ry[3], rz[3], u3.x, u3.y, v3.x, v3.y, t3);
        }
    }
    if (w == 3 && l < 16) {   // dd = 16: each opposite pair once
        const int m = l + 16;
        const ulonglong2 u0 = site[0][0][m], v0 = site[0][1][m];
        const ulonglong2 u1 = site[1][0][m], v1 = site[1][1][m];
        const ulonglong2 u2 = site[2][0][m], v2 = site[2][1][m];
        const ulonglong2 u3 = site[3][0][m], v3 = site[3][1][m];
        grp(rx[0], ry[0], rz[0], u0.x, u0.y, v0.x, v0.y, a01);
        grp(rx[1], ry[1], rz[1], u1.x, u1.y, v1.x, v1.y, a12);
        grp(rx[2], ry[2], rz[2], u2.x, u2.y, v2.x, v2.y, a23);
        grp(rx[3], ry[3], rz[3], u3.x, u3.y, v3.x, v3.y, t3);
    }

    // Row charges applied once (packed); split halves; reduce
    u64 s0 = fma2(a01, (u64)ONE2_PACKED, a02);
    s0 = fma2(a03, (u64)ONE2_PACKED, s0);
    u64 e = fma2(rq[0], s0, 0ULL);
    u64 s1 = fma2(a12, (u64)ONE2_PACKED, a13);
    e = fma2(rq[1], s1, e);
    e = fma2(rq[2], a23, e);
    e = fma2(rq[3], t3, e);
    float eA, eB;
    unpk2(e, eA, eB);
#pragma unroll
    for (int o = 16; o > 0; o >>= 1) {
        eA += __shfl_xor_sync(FULLMASK, eA, o);
        eB += __shfl_xor_sync(FULLMASK, eB, o);
    }
    if (l == 0) {
        warp_sumA[w] = eA;
        warp_sumB[w] = eB;
    }
    __syncthreads();
    if (threadIdx.x == 0) {
        out[fidA] = (warp_sumA[0] + warp_sumA[1]) + (warp_sumA[2] + warp_sumA[3]);
        if (hasB)
            out[fidB] = (warp_sumB[0] + warp_sumB[1]) + (warp_sumB[2] + warp_sumB[3]);
    }
}

extern "C" void kernel_launch(void* const* d_in, const int* in_sizes, int n_in,
                              void* d_out, int out_size) {
    const float* positions = (const float*)d_in[0];  // [N,3] f32
    const float* charges   = (const float*)d_in[1];  // [N]   f32
    float* out = (float*)d_out;                      // [B]   f32

    const int num_frames = out_size;
    const int grid = (num_frames + 1) / 2;
    interacting_sites_kernel<<<grid, S_SITES>>>(positions, charges, out, num_frames);
}